// round 1
// baseline (speedup 1.0000x reference)
#include <cuda_runtime.h>
#include <cuda_bf16.h>
#include <math.h>

#define B_  8
#define L_  2048
#define E_  100
#define FM_ 50
#define Y_  8921
#define K_  9

#define TY  16          // labels per block (attn kernel)
#define LC  256         // l-chunk staged in smem
#define HS_STRIDE 258   // padded row stride for h_s
#define NYT 558         // ceil(Y_/TY)

// scratch (static device allocations are allowed)
__device__ float g_h[(size_t)B_ * L_ * FM_];          // [b][l][f]  3.28 MB
__device__ float g_losspart[B_ * NYT];

// ---------------------------------------------------------------------------
// Kernel 1: embedding gather + conv1d(K=9, same) + bias + tanh  -> g_h[b][l][f]
// grid (32, 8), 256 threads. f = tid>>2 (active <50), lg = tid&3 -> 16 l's each.
// ---------------------------------------------------------------------------
__global__ void __launch_bounds__(256) conv_kernel(
    const int* __restrict__ tokens,
    const float* __restrict__ embed_W,
    const float* __restrict__ conv_w,
    const float* __restrict__ conv_b)
{
    __shared__ int   tok_s[72];
    __shared__ float x_s[72][21];          // e-chunk of 20 (pad 21)
    __shared__ float w_s[50][20][9];       // f, e-chunk, k

    const int tid   = threadIdx.x;
    const int b     = blockIdx.y;
    const int lbase = blockIdx.x * 64;

    if (tid < 72) {
        int gl = lbase + tid - 4;
        tok_s[tid] = (gl >= 0 && gl < L_) ? tokens[b * L_ + gl] : -1;
    }
    __syncthreads();

    const int f  = tid >> 2;     // 0..63 (valid < 50)
    const int lg = tid & 3;
    const int l0 = lg * 16;

    float acc[16];
#pragma unroll
    for (int j = 0; j < 16; j++) acc[j] = 0.f;

    for (int ec = 0; ec < 5; ec++) {
        // stage x chunk: 72 positions x 20 embedding dims
        for (int idx = tid; idx < 72 * 20; idx += 256) {
            int i = idx / 20, e = idx % 20;
            int t = tok_s[i];
            x_s[i][e] = (t >= 0) ? embed_W[(size_t)t * E_ + ec * 20 + e] : 0.f;
        }
        // stage w chunk: 50 x 20 x 9
        for (int idx = tid; idx < 50 * 20 * 9; idx += 256) {
            int ff = idx / 180, r = idx % 180;
            w_s[ff][r / 9][r % 9] = conv_w[ff * (E_ * K_) + ec * 180 + r];
        }
        __syncthreads();

        if (f < FM_) {
            for (int e = 0; e < 20; e++) {
                float xv[24];
#pragma unroll
                for (int t = 0; t < 24; t++) xv[t] = x_s[l0 + t][e];
                float wv[9];
#pragma unroll
                for (int k = 0; k < 9; k++) wv[k] = w_s[f][e][k];
#pragma unroll
                for (int k = 0; k < 9; k++)
#pragma unroll
                    for (int j = 0; j < 16; j++)
                        acc[j] += xv[j + k] * wv[k];
            }
        }
        __syncthreads();
    }

    if (f < FM_) {
        float bias = conv_b[f];
#pragma unroll
        for (int j = 0; j < 16; j++) {
            int l = lbase + l0 + j;
            g_h[((size_t)(b * L_) + l) * FM_ + f] = tanhf(acc[j] + bias);
        }
    }
}

// ---------------------------------------------------------------------------
// Kernel 2: fused label-attention.
// block = (y-tile of 16, b). 256 threads = 8 warps; warp handles 2 labels.
// pass1: s=h.U, q=h.final per l-chunk, scores kept in smem, online (m,Z,R).
// pass2: alpha = exp(s-m)/Z written to gmem; yhat = sigmoid(R/Z + bias).
// ---------------------------------------------------------------------------
__global__ void __launch_bounds__(256, 1) attn_kernel(
    const float* __restrict__ U_w,
    const float* __restrict__ final_w,
    const float* __restrict__ final_b,
    const float* __restrict__ target,
    float* __restrict__ out_yhat,
    float* __restrict__ out_alpha,
    int write_alpha)
{
    extern __shared__ float sm[];
    float* s_smem  = sm;                              // TY * L_      = 32768
    float* h_s     = s_smem + TY * L_;                // 50 * 258     = 12900
    float* u_sT    = h_s + FM_ * HS_STRIDE;           // 50 * 16      = 800
    float* f_sT    = u_sT + FM_ * TY;                 // 50 * 16      = 800
    float* loss_red= f_sT + FM_ * TY;                 // TY

    const int tid  = threadIdx.x;
    const int lane = tid & 31;
    const int warp = tid >> 5;
    const int b    = blockIdx.y;
    const int y0t  = blockIdx.x * TY;

    // stage U / final transposed: [f][y] so a warp reads its 2 labels as float2
    for (int idx = tid; idx < FM_ * TY; idx += 256) {
        int f = idx / TY, y = idx % TY;
        int gy = y0t + y;
        float uv = 0.f, fv = 0.f;
        if (gy < Y_) { uv = U_w[gy * FM_ + f]; fv = final_w[gy * FM_ + f]; }
        u_sT[f * TY + y] = uv;
        f_sT[f * TY + y] = fv;
    }
    if (tid < TY) loss_red[tid] = 0.f;

    const int yl0 = warp * 2;          // even
    const int gy0 = y0t + yl0, gy1 = gy0 + 1;

    float m0 = -1e30f, m1 = -1e30f;
    float Z0 = 0.f, Z1 = 0.f, R0 = 0.f, R1 = 0.f;

    for (int ch = 0; ch < L_ / LC; ch++) {
        const int lb = ch * LC;
        __syncthreads();   // previous chunk's readers done (also covers u/loss init)
        for (int idx = tid; idx < LC * FM_; idx += 256) {
            int l = idx / FM_, f = idx % FM_;
            h_s[f * HS_STRIDE + l] = g_h[((size_t)(b * L_ + lb + l)) * FM_ + f];
        }
        __syncthreads();

        float s0[8], s1[8], q0[8], q1[8];
#pragma unroll
        for (int j = 0; j < 8; j++) { s0[j]=0.f; s1[j]=0.f; q0[j]=0.f; q1[j]=0.f; }

        const float* hp = h_s + 2 * lane;
        const float* up = u_sT + yl0;
        const float* fp = f_sT + yl0;
#pragma unroll 2
        for (int f = 0; f < FM_; f++) {
            float2 u01  = *(const float2*)(up);
            float2 fn01 = *(const float2*)(fp);
#pragma unroll
            for (int j = 0; j < 4; j++) {
                float2 hv = *(const float2*)(hp + 64 * j);
                s0[2*j]   += hv.x * u01.x;  s0[2*j+1] += hv.y * u01.x;
                s1[2*j]   += hv.x * u01.y;  s1[2*j+1] += hv.y * u01.y;
                q0[2*j]   += hv.x * fn01.x; q0[2*j+1] += hv.y * fn01.x;
                q1[2*j]   += hv.x * fn01.y; q1[2*j+1] += hv.y * fn01.y;
            }
            hp += HS_STRIDE; up += TY; fp += TY;
        }

        // persist scores (each warp owns its two rows)
        {
            float* sp0 = s_smem + yl0 * L_ + lb + 2 * lane;
            float* sp1 = sp0 + L_;
#pragma unroll
            for (int j = 0; j < 4; j++) {
                *(float2*)(sp0 + 64 * j) = make_float2(s0[2*j], s0[2*j+1]);
                *(float2*)(sp1 + 64 * j) = make_float2(s1[2*j], s1[2*j+1]);
            }
        }

        // online softmax + attended projection accumulation
        float cm0 = s0[0], cm1 = s1[0];
#pragma unroll
        for (int j = 1; j < 8; j++) { cm0 = fmaxf(cm0, s0[j]); cm1 = fmaxf(cm1, s1[j]); }
#pragma unroll
        for (int o = 16; o > 0; o >>= 1) {
            cm0 = fmaxf(cm0, __shfl_xor_sync(0xffffffffu, cm0, o));
            cm1 = fmaxf(cm1, __shfl_xor_sync(0xffffffffu, cm1, o));
        }
        float nm0 = fmaxf(m0, cm0), nm1 = fmaxf(m1, cm1);
        float se0 = 0.f, se1 = 0.f, sq0 = 0.f, sq1 = 0.f;
#pragma unroll
        for (int j = 0; j < 8; j++) {
            float e0 = __expf(s0[j] - nm0); se0 += e0; sq0 += e0 * q0[j];
            float e1 = __expf(s1[j] - nm1); se1 += e1; sq1 += e1 * q1[j];
        }
#pragma unroll
        for (int o = 16; o > 0; o >>= 1) {
            se0 += __shfl_xor_sync(0xffffffffu, se0, o);
            sq0 += __shfl_xor_sync(0xffffffffu, sq0, o);
            se1 += __shfl_xor_sync(0xffffffffu, se1, o);
            sq1 += __shfl_xor_sync(0xffffffffu, sq1, o);
        }
        float sc0 = __expf(m0 - nm0), sc1 = __expf(m1 - nm1);
        Z0 = Z0 * sc0 + se0; R0 = R0 * sc0 + sq0; m0 = nm0;
        Z1 = Z1 * sc1 + se1; R1 = R1 * sc1 + sq1; m1 = nm1;
    }

    // yhat + per-label BCE term
    if (lane == 0) {
        if (gy0 < Y_) {
            float r  = R0 / Z0 + final_b[gy0];
            float yh = 1.f / (1.f + expf(-r));
            out_yhat[b * Y_ + gy0] = yh;
            float t = target[b * Y_ + gy0];
            loss_red[yl0] = t * logf(yh + 1e-12f) + (1.f - t) * logf(1.f - yh + 1e-12f);
        }
        if (gy1 < Y_) {
            float r  = R1 / Z1 + final_b[gy1];
            float yh = 1.f / (1.f + expf(-r));
            out_yhat[b * Y_ + gy1] = yh;
            float t = target[b * Y_ + gy1];
            loss_red[yl0 + 1] = t * logf(yh + 1e-12f) + (1.f - t) * logf(1.f - yh + 1e-12f);
        }
    }
    __syncthreads();
    if (tid == 0) {
        float s = 0.f;
#pragma unroll
        for (int i = 0; i < TY; i++) s += loss_red[i];
        g_losspart[b * gridDim.x + blockIdx.x] = s;
    }

    // pass 2: normalize scores -> alpha
    if (write_alpha) {
        float iZ0 = 1.f / Z0, iZ1 = 1.f / Z1;
        if (gy0 < Y_) {
            float* ap = out_alpha + ((size_t)b * Y_ + gy0) * L_;
            const float* sp = s_smem + yl0 * L_;
            for (int l = lane; l < L_; l += 32)
                ap[l] = __expf(sp[l] - m0) * iZ0;
        }
        if (gy1 < Y_) {
            float* ap = out_alpha + ((size_t)b * Y_ + gy1) * L_;
            const float* sp = s_smem + (yl0 + 1) * L_;
            for (int l = lane; l < L_; l += 32)
                ap[l] = __expf(sp[l] - m1) * iZ1;
        }
    }
}

// ---------------------------------------------------------------------------
// Kernel 3: deterministic loss reduction
// ---------------------------------------------------------------------------
__global__ void loss_kernel(float* __restrict__ out_loss, int npart)
{
    __shared__ float red[256];
    float s = 0.f;
    for (int i = threadIdx.x; i < npart; i += 256) s += g_losspart[i];
    red[threadIdx.x] = s;
    __syncthreads();
    for (int o = 128; o > 0; o >>= 1) {
        if (threadIdx.x < o) red[threadIdx.x] += red[threadIdx.x + o];
        __syncthreads();
    }
    if (threadIdx.x == 0) *out_loss = -red[0] / (float)(B_ * Y_);
}

// ---------------------------------------------------------------------------
extern "C" void kernel_launch(void* const* d_in, const int* in_sizes, int n_in,
                              void* d_out, int out_size)
{
    const int*   tokens  = (const int*)  d_in[0];
    const float* target  = (const float*)d_in[1];
    const float* embed_W = (const float*)d_in[2];
    const float* conv_w  = (const float*)d_in[3];
    const float* conv_b  = (const float*)d_in[4];
    const float* U_w     = (const float*)d_in[5];
    const float* final_w = (const float*)d_in[6];
    const float* final_b = (const float*)d_in[7];
    float* out = (float*)d_out;

    const long long yhat_n  = (long long)B_ * Y_;                 // 71368
    const long long total_n = yhat_n + 1 + (long long)B_ * Y_ * L_;
    int write_loss  = (out_size >= (int)(yhat_n + 1)) ? 1 : 0;
    int write_alpha = ((long long)out_size >= total_n) ? 1 : 0;

    const int smem_bytes = (TY * L_ + FM_ * HS_STRIDE + 2 * FM_ * TY + TY) * 4;
    cudaFuncSetAttribute(attn_kernel, cudaFuncAttributeMaxDynamicSharedMemorySize,
                         smem_bytes);

    conv_kernel<<<dim3(L_ / 64, B_), 256>>>(tokens, embed_W, conv_w, conv_b);

    float* out_alpha = out + yhat_n + 1;
    attn_kernel<<<dim3(NYT, B_), 256, smem_bytes>>>(
        U_w, final_w, final_b, target, out, out_alpha, write_alpha);

    if (write_loss)
        loss_kernel<<<1, 256>>>(out + yhat_n, B_ * NYT);
}